// round 14
// baseline (speedup 1.0000x reference)
#include <cuda_runtime.h>
#include <cuda_bf16.h>
#include <cstdint>
#include <math.h>

// Problem dims
#define BB 4
#define SS 1024
#define DM 1024
#define NH 16
#define DK 64
#define DV 64

// Scratch for projected Q/K/V in [b, h, s, d] layout (stored tf32-rounded)
__device__ float g_Q[BB * NH * SS * DK];
__device__ float g_K[BB * NH * SS * DK];
__device__ float g_V[BB * NH * SS * DV];

// ---------------------------------------------------------------------------
// helpers
// ---------------------------------------------------------------------------
__device__ __forceinline__ uint32_t f2tf32(float x) {
    uint32_t r;
    asm("cvt.rna.tf32.f32 %0, %1;" : "=r"(r) : "f"(x));
    return r;
}
__device__ __forceinline__ float rnd_tf32(float x) {
    return __uint_as_float(f2tf32(x));
}

__device__ __forceinline__ void mma_tf32(float c[4], const uint32_t a[4], const uint32_t b[2]) {
    asm volatile(
        "mma.sync.aligned.m16n8k8.row.col.f32.tf32.tf32.f32 "
        "{%0,%1,%2,%3}, {%4,%5,%6,%7}, {%8,%9}, {%0,%1,%2,%3};"
        : "+f"(c[0]), "+f"(c[1]), "+f"(c[2]), "+f"(c[3])
        : "r"(a[0]), "r"(a[1]), "r"(a[2]), "r"(a[3]), "r"(b[0]), "r"(b[1]));
}

__device__ __forceinline__ void ldsm_x4(uint32_t r[4], uint32_t addr) {
    asm volatile("ldmatrix.sync.aligned.m8n8.x4.shared.b16 {%0,%1,%2,%3}, [%4];"
                 : "=r"(r[0]), "=r"(r[1]), "=r"(r[2]), "=r"(r[3]) : "r"(addr));
}

__device__ __forceinline__ void cp16(uint32_t smem, const void* g) {
    asm volatile("cp.async.cg.shared.global [%0], [%1], 16;" :: "r"(smem), "l"(g));
}
#define CP_COMMIT() asm volatile("cp.async.commit_group;")
#define CP_WAIT0()  asm volatile("cp.async.wait_group 0;")
#define CP_WAIT1()  asm volatile("cp.async.wait_group 1;")

// ---------------------------------------------------------------------------
// Projection GEMM, tf32 mma.sync (unchanged; measured ~193us).
// ---------------------------------------------------------------------------
#define ASTR 36
#define WSTR 136

__global__ __launch_bounds__(256, 2) void proj_mma_kernel(
    const float* __restrict__ xq, const float* __restrict__ xk, const float* __restrict__ xv,
    const float* __restrict__ wq, const float* __restrict__ wk, const float* __restrict__ wv,
    const float* __restrict__ bq, const float* __restrict__ bk, const float* __restrict__ bv)
{
    __shared__ float As[128 * ASTR];
    __shared__ float Ws[32 * WSTR];

    const float* X; const float* W; const float* bias; float* out;
    int which = blockIdx.z;
    if (which == 0)      { X = xq; W = wq; bias = bq; out = g_Q; }
    else if (which == 1) { X = xk; W = wk; bias = bk; out = g_K; }
    else                 { X = xv; W = wv; bias = bv; out = g_V; }

    const int tid  = threadIdx.x;
    const int warp = tid >> 5;
    const int lane = tid & 31;
    const int wm   = warp >> 2;
    const int wn   = warp & 3;
    const int tileM = blockIdx.y * 128;
    const int tileN = blockIdx.x * 128;

    const int lrow = (lane & 7) + ((lane >> 3) & 1) * 8;
    const int lkc  = (lane >> 4) * 4;
    const int a_lane_off = lrow * ASTR + lkc;

    const uint32_t As_base = (uint32_t)__cvta_generic_to_shared(As);

    float acc[4][4][4];
#pragma unroll
    for (int mt = 0; mt < 4; mt++)
#pragma unroll
        for (int nt = 0; nt < 4; nt++)
#pragma unroll
            for (int i = 0; i < 4; i++) acc[mt][nt][i] = 0.0f;

    float4 xr[4], wr[4];
#pragma unroll
    for (int p = 0; p < 4; p++) {
        int id = tid + 256 * p;
        xr[p] = *(const float4*)&X[(size_t)(tileM + (id >> 3)) * DM + (id & 7) * 4];
        wr[p] = *(const float4*)&W[(size_t)(id >> 5) * DM + tileN + (id & 31) * 4];
    }

    for (int k0 = 0; k0 < DM; k0 += 32) {
        __syncthreads();
#pragma unroll
        for (int p = 0; p < 4; p++) {
            int id = tid + 256 * p;
            float4 xv4 = make_float4(rnd_tf32(xr[p].x), rnd_tf32(xr[p].y),
                                     rnd_tf32(xr[p].z), rnd_tf32(xr[p].w));
            float4 wv4 = make_float4(rnd_tf32(wr[p].x), rnd_tf32(wr[p].y),
                                     rnd_tf32(wr[p].z), rnd_tf32(wr[p].w));
            *(float4*)&As[(id >> 3) * ASTR + (id & 7) * 4] = xv4;
            *(float4*)&Ws[(id >> 5) * WSTR + (id & 31) * 4] = wv4;
        }
        __syncthreads();

        if (k0 + 32 < DM) {
#pragma unroll
            for (int p = 0; p < 4; p++) {
                int id = tid + 256 * p;
                xr[p] = *(const float4*)&X[(size_t)(tileM + (id >> 3)) * DM + k0 + 32 + (id & 7) * 4];
                wr[p] = *(const float4*)&W[(size_t)(k0 + 32 + (id >> 5)) * DM + tileN + (id & 31) * 4];
            }
        }

#pragma unroll
        for (int ks = 0; ks < 4; ks++) {
            uint32_t a[4][4];
#pragma unroll
            for (int mt = 0; mt < 4; mt++) {
                uint32_t addr = As_base +
                    4u * (uint32_t)((wm * 64 + mt * 16) * ASTR + ks * 8 + a_lane_off);
                ldsm_x4(a[mt], addr);
            }
            uint32_t bfr[4][2];
#pragma unroll
            for (int nt = 0; nt < 4; nt++) {
                int col = wn * 32 + nt * 8 + (lane >> 2);
                int krow = ks * 8 + (lane & 3);
                bfr[nt][0] = __float_as_uint(Ws[krow * WSTR + col]);
                bfr[nt][1] = __float_as_uint(Ws[(krow + 4) * WSTR + col]);
            }
#pragma unroll
            for (int mt = 0; mt < 4; mt++)
#pragma unroll
                for (int nt = 0; nt < 4; nt++)
                    mma_tf32(acc[mt][nt], a[mt], bfr[nt]);
        }
    }

#pragma unroll
    for (int mt = 0; mt < 4; mt++) {
        int r0 = tileM + wm * 64 + mt * 16 + (lane >> 2);
#pragma unroll
        for (int nt = 0; nt < 4; nt++) {
            int c0 = tileN + wn * 32 + nt * 8 + (lane & 3) * 2;
            int h = c0 >> 6, d = c0 & 63;
            float bv0 = bias[c0], bv1 = bias[c0 + 1];
#pragma unroll
            for (int half = 0; half < 2; half++) {
                int r = r0 + half * 8;
                int bb = r >> 10, s = r & (SS - 1);
                float2 o = make_float2(rnd_tf32(acc[mt][nt][half * 2 + 0] + bv0),
                                       rnd_tf32(acc[mt][nt][half * 2 + 1] + bv1));
                *(float2*)&out[(((size_t)(bb * NH + h) * SS + s) << 6) + d] = o;
            }
        }
    }
}

// ---------------------------------------------------------------------------
// Fused attention: per-warp decoupled pipelines. 32 q-rows, 8 warps.
// Each warp owns its (wmt = m16 tile, wns = 16-col n-slice) and loads its
// OWN K n-slice (16x64) / V column-slice (64x16) into private double-buffered
// slabs via its own cp.async groups. NO __syncthreads in the tile loops —
// only: after Q load, after scores, after softmax.
// Iter discipline: wait tile t (own group) -> compute t -> issue t+2 into
// buf (t&1) which t's compute just finished reading. No WAR hazard, no sync.
// ---------------------------------------------------------------------------
#define QR 32
#define KTL 64          // K/V tile rows
#define NTK 16          // number of K tiles (= number of V tiles)
#define SQS 68
#define SSS 1028
#define KSTR 68         // K slab row stride (16 rows x 64 floats)
#define VSTR 20         // V slab row stride (64 rows x 16 floats)
#define SLB 1280        // floats per slab buffer (max(16*68, 64*20))
#define ATTN_SMEM_FLOATS (QR * SQS + 16 * SLB + QR * SSS)
#define ATTN_SMEM_BYTES (ATTN_SMEM_FLOATS * 4)

__global__ __launch_bounds__(256, 1) void attn_kernel(
    float* __restrict__ ctx_out, float* __restrict__ attn_out)
{
    extern __shared__ float sm[];
    float* sQ    = sm;                    // 32 x 68
    float* sSlab = sQ + QR * SQS;         // 8 warps x 2 bufs x 1280
    float* sS    = sSlab + 16 * SLB;      // 32 x 1028

    const int tid  = threadIdx.x;
    const int warp = tid >> 5;      // 0..7
    const int lane = tid & 31;
    const int wmt  = warp >> 2;     // 0..1 : m16 tile
    const int wns  = warp & 3;      // 0..3 : 16-col n-slice
    const int qt = blockIdx.x;
    const int h  = blockIdx.y;
    const int b  = blockIdx.z;

    const float* Qb = g_Q + ((size_t)(b * NH + h) * SS + qt * QR) * DK;
    const float* Kb = g_K + (size_t)(b * NH + h) * SS * DK;
    const float* Vb = g_V + (size_t)(b * NH + h) * SS * DV;

    const int lrow = (lane & 7) + ((lane >> 3) & 1) * 8;
    const int lkc  = (lane >> 4) * 4;
    const uint32_t sQ_base = (uint32_t)__cvta_generic_to_shared(sQ);
    const uint32_t sS_base = (uint32_t)__cvta_generic_to_shared(sS);

    // this warp's private slab buffers
    float* const myslab_f[2] = { sSlab + (warp * 2 + 0) * SLB,
                                 sSlab + (warp * 2 + 1) * SLB };
    const uint32_t myslab_u[2] = {
        (uint32_t)__cvta_generic_to_shared(myslab_f[0]),
        (uint32_t)__cvta_generic_to_shared(myslab_f[1])
    };

    // K-slab ldmatrix.x4 lane offset: block j = lane>>3 -> (nt = j>>1, khalf = j&1)
    const int bj = lane >> 3;
    const int kb_off = ((bj >> 1) * 8 + (lane & 7)) * KSTR + (bj & 1) * 4;

    // ---- Q tile (plain loads) ----
#pragma unroll
    for (int p = 0; p < 2; p++) {
        int id = tid + 256 * p;
        int row = id >> 4, c4 = (id & 15) * 4;
        *(float4*)&sQ[row * SQS + c4] = *(const float4*)&Qb[row * DK + c4];
    }
    __syncthreads();

    // Preload Q fragments for this warp's m16 tile (raw bits, pre-rounded)
    uint32_t aq[8][4];
#pragma unroll
    for (int ks = 0; ks < 8; ks++)
        ldsm_x4(aq[ks], sQ_base + 4u * (uint32_t)((wmt * 16 + lrow) * SQS + ks * 8 + lkc));

    // ---- per-warp tile issue helpers (8 cp16 per tile) ----
    // K tile t: 16 rows (our n-slice) x 64 cols
    auto issueK = [&](int t) {
        const float* src = &Kb[(size_t)(t * KTL + wns * 16) * DK];
        uint32_t dst = myslab_u[t & 1];
#pragma unroll
        for (int p = 0; p < 8; p++) {
            int id = p * 32 + lane;
            int row = id >> 4, c4 = (id & 15) * 4;
            cp16(dst + 4u * (uint32_t)(row * KSTR + c4), &src[row * DK + c4]);
        }
        CP_COMMIT();
    };
    // V tile t: 64 rows x 16 cols (our d-slice)
    auto issueV = [&](int t) {
        const float* src = &Vb[(size_t)(t * KTL) * DV + wns * 16];
        uint32_t dst = myslab_u[t & 1];
#pragma unroll
        for (int p = 0; p < 8; p++) {
            int id = p * 32 + lane;
            int kr = id >> 2, c4 = (id & 3) * 4;
            cp16(dst + 4u * (uint32_t)(kr * VSTR + c4), &src[kr * DV + c4]);
        }
        CP_COMMIT();
    };

    // prologue: K0, K1 in flight (own groups)
    issueK(0);
    issueK(1);

    // ---- Scores: S = (Q K^T)/8, 16 tiles, per-warp pipeline, NO barriers ----
    for (int kt = 0; kt < NTK; kt++) {
        CP_WAIT1();    // own groups: tile kt complete (kt+1 pending)

        const uint32_t kbuf = myslab_u[kt & 1] + 4u * (uint32_t)kb_off;
        float c[2][4];
#pragma unroll
        for (int nt = 0; nt < 2; nt++)
#pragma unroll
            for (int i = 0; i < 4; i++) c[nt][i] = 0.0f;

#pragma unroll
        for (int ks = 0; ks < 8; ks++) {
            uint32_t bfr[4];
            ldsm_x4(bfr, kbuf + 4u * (uint32_t)(ks * 8));
            mma_tf32(c[0], aq[ks], &bfr[0]);
            mma_tf32(c[1], aq[ks], &bfr[2]);
        }

        // issue tile kt+2 (buf kt&1 just finished being read)
        int g = kt + 2;
        if (g < NTK) issueK(g);
        else         issueV(g - NTK);

        // epilogue: this warp's private S region
#pragma unroll
        for (int nt = 0; nt < 2; nt++) {
            int r = wmt * 16 + (lane >> 2);
            int col = kt * KTL + wns * 16 + nt * 8 + 2 * (lane & 3);
            *(float2*)&sS[r * SSS + col] = make_float2(c[nt][0] * 0.125f, c[nt][1] * 0.125f);
            *(float2*)&sS[(r + 8) * SSS + col] = make_float2(c[nt][2] * 0.125f, c[nt][3] * 0.125f);
        }
    }
    __syncthreads();    // all warps' S visible (V0/V1 still in flight per warp)

    // ---- Softmax (4 rows/warp); raw P -> gmem, tf32 P -> smem ----
#pragma unroll
    for (int rr = 0; rr < 4; rr++) {
        int r = warp * 4 + rr;
        float* row = sS + r * SSS;
        float mx = -3.0e38f;
#pragma unroll
        for (int k = 0; k < 8; k++) {
            float4 v = *(const float4*)&row[lane * 4 + 128 * k];
            mx = fmaxf(mx, fmaxf(fmaxf(v.x, v.y), fmaxf(v.z, v.w)));
        }
#pragma unroll
        for (int o = 16; o > 0; o >>= 1) mx = fmaxf(mx, __shfl_xor_sync(0xffffffffu, mx, o));
        float sum = 0.0f;
        float4 e[8];
#pragma unroll
        for (int k = 0; k < 8; k++) {
            float4 v = *(const float4*)&row[lane * 4 + 128 * k];
            e[k].x = __expf(v.x - mx); e[k].y = __expf(v.y - mx);
            e[k].z = __expf(v.z - mx); e[k].w = __expf(v.w - mx);
            sum += e[k].x + e[k].y + e[k].z + e[k].w;
        }
#pragma unroll
        for (int o = 16; o > 0; o >>= 1) sum += __shfl_xor_sync(0xffffffffu, sum, o);
        float inv = 1.0f / sum;
        float* arow = attn_out + ((size_t)(b * NH + h) * SS + qt * QR + r) * SS;
#pragma unroll
        for (int k = 0; k < 8; k++) {
            float4 p = make_float4(e[k].x * inv, e[k].y * inv, e[k].z * inv, e[k].w * inv);
            *(float4*)&arow[lane * 4 + 128 * k] = p;
            float4 pr = make_float4(rnd_tf32(p.x), rnd_tf32(p.y),
                                    rnd_tf32(p.z), rnd_tf32(p.w));
            *(float4*)&row[lane * 4 + 128 * k] = pr;
        }
    }
    __syncthreads();    // all P visible before cross-warp A-frag ldsm

    // ---- PV: context = P @ V, 16 tiles, per-warp pipeline, NO barriers ----
    float acc2[2][4];
#pragma unroll
    for (int nt = 0; nt < 2; nt++)
#pragma unroll
        for (int i = 0; i < 4; i++) acc2[nt][i] = 0.0f;

    for (int vt = 0; vt < NTK; vt++) {
        if (vt == NTK - 1) CP_WAIT0();
        else               CP_WAIT1();    // own V tile vt complete

        const float* vb = myslab_f[vt & 1];
#pragma unroll
        for (int ks = 0; ks < 8; ks++) {
            uint32_t ap[4];
            ldsm_x4(ap, sS_base +
                    4u * (uint32_t)((wmt * 16 + lrow) * SSS + vt * KTL + ks * 8 + lkc));
            uint32_t bfr[2][2];
#pragma unroll
            for (int nt = 0; nt < 2; nt++) {
                int col = nt * 8 + (lane >> 2);
                int krow = ks * 8 + (lane & 3);
                bfr[nt][0] = __float_as_uint(vb[krow * VSTR + col]);
                bfr[nt][1] = __float_as_uint(vb[(krow + 4) * VSTR + col]);
            }
            mma_tf32(acc2[0], ap, bfr[0]);
            mma_tf32(acc2[1], ap, bfr[1]);
        }

        if (vt + 2 < NTK) issueV(vt + 2);   // buf vt&1 just freed
    }

    // Write context in [b, s, h*64 + d]
#pragma unroll
    for (int nt = 0; nt < 2; nt++) {
        int r = qt * QR + wmt * 16 + (lane >> 2);
        int col = h * DV + wns * 16 + nt * 8 + 2 * (lane & 3);
        *(float2*)&ctx_out[((size_t)b * SS + r) * (NH * DV) + col] =
            make_float2(acc2[nt][0], acc2[nt][1]);
        *(float2*)&ctx_out[((size_t)b * SS + r + 8) * (NH * DV) + col] =
            make_float2(acc2[nt][2], acc2[nt][3]);
    }
}

// ---------------------------------------------------------------------------
// Launch
// ---------------------------------------------------------------------------
extern "C" void kernel_launch(void* const* d_in, const int* in_sizes, int n_in,
                              void* d_out, int out_size)
{
    const float* q  = (const float*)d_in[0];
    const float* k  = (const float*)d_in[1];
    const float* v  = (const float*)d_in[2];
    const float* wq = (const float*)d_in[3];
    const float* wk = (const float*)d_in[4];
    const float* wv = (const float*)d_in[5];
    const float* bq = (const float*)d_in[6];
    const float* bk = (const float*)d_in[7];
    const float* bv = (const float*)d_in[8];
    // d_in[9] = attn_mask (falsy) -> no masking

    float* ctx  = (float*)d_out;
    float* attn = (float*)d_out + (size_t)BB * SS * NH * DV;

    (void)cudaFuncSetAttribute(attn_kernel,
                               cudaFuncAttributeMaxDynamicSharedMemorySize,
                               ATTN_SMEM_BYTES);

    dim3 pgrid(DM / 128, (BB * SS) / 128, 3);
    proj_mma_kernel<<<pgrid, 256>>>(q, k, v, wq, wk, wv, bq, bk, bv);

    dim3 agrid(SS / QR, NH, BB);
    attn_kernel<<<agrid, 256, ATTN_SMEM_BYTES>>>(ctx, attn);
}

// round 16
// speedup vs baseline: 1.3848x; 1.3848x over previous
#include <cuda_runtime.h>
#include <cuda_fp16.h>
#include <cstdint>
#include <math.h>

// Problem dims
#define BB 4
#define SS 1024
#define DM 1024
#define NH 16
#define DK 64
#define DV 64

// Scratch for projected Q/K/V in [b, h, s, d] layout, stored FP16
__device__ __half g_Q[BB * NH * SS * DK];
__device__ __half g_K[BB * NH * SS * DK];
__device__ __half g_V[BB * NH * SS * DV];

// ---------------------------------------------------------------------------
// helpers
// ---------------------------------------------------------------------------
__device__ __forceinline__ uint32_t f2tf32(float x) {
    uint32_t r;
    asm("cvt.rna.tf32.f32 %0, %1;" : "=r"(r) : "f"(x));
    return r;
}
__device__ __forceinline__ float rnd_tf32(float x) {
    return __uint_as_float(f2tf32(x));
}

__device__ __forceinline__ void mma_tf32(float c[4], const uint32_t a[4], const uint32_t b[2]) {
    asm volatile(
        "mma.sync.aligned.m16n8k8.row.col.f32.tf32.tf32.f32 "
        "{%0,%1,%2,%3}, {%4,%5,%6,%7}, {%8,%9}, {%0,%1,%2,%3};"
        : "+f"(c[0]), "+f"(c[1]), "+f"(c[2]), "+f"(c[3])
        : "r"(a[0]), "r"(a[1]), "r"(a[2]), "r"(a[3]), "r"(b[0]), "r"(b[1]));
}

// fp16 mma, fp32 accumulate
__device__ __forceinline__ void mma_f16(float c[4], const uint32_t a[4], const uint32_t b[2]) {
    asm volatile(
        "mma.sync.aligned.m16n8k16.row.col.f32.f16.f16.f32 "
        "{%0,%1,%2,%3}, {%4,%5,%6,%7}, {%8,%9}, {%0,%1,%2,%3};"
        : "+f"(c[0]), "+f"(c[1]), "+f"(c[2]), "+f"(c[3])
        : "r"(a[0]), "r"(a[1]), "r"(a[2]), "r"(a[3]), "r"(b[0]), "r"(b[1]));
}

__device__ __forceinline__ void ldsm_x4(uint32_t r[4], uint32_t addr) {
    asm volatile("ldmatrix.sync.aligned.m8n8.x4.shared.b16 {%0,%1,%2,%3}, [%4];"
                 : "=r"(r[0]), "=r"(r[1]), "=r"(r[2]), "=r"(r[3]) : "r"(addr));
}
__device__ __forceinline__ void ldsm_x4_t(uint32_t r[4], uint32_t addr) {
    asm volatile("ldmatrix.sync.aligned.m8n8.x4.trans.shared.b16 {%0,%1,%2,%3}, [%4];"
                 : "=r"(r[0]), "=r"(r[1]), "=r"(r[2]), "=r"(r[3]) : "r"(addr));
}

__device__ __forceinline__ void cp16(uint32_t smem, const void* g) {
    asm volatile("cp.async.cg.shared.global [%0], [%1], 16;" :: "r"(smem), "l"(g));
}
#define CP_COMMIT() asm volatile("cp.async.commit_group;")
#define CP_WAIT0()  asm volatile("cp.async.wait_group 0;")
#define CP_WAIT1()  asm volatile("cp.async.wait_group 1;")
#define CP_WAIT2()  asm volatile("cp.async.wait_group 2;")

// ---------------------------------------------------------------------------
// Projection GEMM, tf32 mma.sync (proven ~193us); epilogue emits FP16.
// ---------------------------------------------------------------------------
#define ASTR 36
#define WSTR 136

__global__ __launch_bounds__(256, 2) void proj_mma_kernel(
    const float* __restrict__ xq, const float* __restrict__ xk, const float* __restrict__ xv,
    const float* __restrict__ wq, const float* __restrict__ wk, const float* __restrict__ wv,
    const float* __restrict__ bq, const float* __restrict__ bk, const float* __restrict__ bv)
{
    __shared__ float As[128 * ASTR];
    __shared__ float Ws[32 * WSTR];

    const float* X; const float* W; const float* bias; __half* out;
    int which = blockIdx.z;
    if (which == 0)      { X = xq; W = wq; bias = bq; out = g_Q; }
    else if (which == 1) { X = xk; W = wk; bias = bk; out = g_K; }
    else                 { X = xv; W = wv; bias = bv; out = g_V; }

    const int tid  = threadIdx.x;
    const int warp = tid >> 5;
    const int lane = tid & 31;
    const int wm   = warp >> 2;
    const int wn   = warp & 3;
    const int tileM = blockIdx.y * 128;
    const int tileN = blockIdx.x * 128;

    const int lrow = (lane & 7) + ((lane >> 3) & 1) * 8;
    const int lkc  = (lane >> 4) * 4;
    const int a_lane_off = lrow * ASTR + lkc;

    const uint32_t As_base = (uint32_t)__cvta_generic_to_shared(As);

    float acc[4][4][4];
#pragma unroll
    for (int mt = 0; mt < 4; mt++)
#pragma unroll
        for (int nt = 0; nt < 4; nt++)
#pragma unroll
            for (int i = 0; i < 4; i++) acc[mt][nt][i] = 0.0f;

    float4 xr[4], wr[4];
#pragma unroll
    for (int p = 0; p < 4; p++) {
        int id = tid + 256 * p;
        xr[p] = *(const float4*)&X[(size_t)(tileM + (id >> 3)) * DM + (id & 7) * 4];
        wr[p] = *(const float4*)&W[(size_t)(id >> 5) * DM + tileN + (id & 31) * 4];
    }

    for (int k0 = 0; k0 < DM; k0 += 32) {
        __syncthreads();
#pragma unroll
        for (int p = 0; p < 4; p++) {
            int id = tid + 256 * p;
            float4 xv4 = make_float4(rnd_tf32(xr[p].x), rnd_tf32(xr[p].y),
                                     rnd_tf32(xr[p].z), rnd_tf32(xr[p].w));
            float4 wv4 = make_float4(rnd_tf32(wr[p].x), rnd_tf32(wr[p].y),
                                     rnd_tf32(wr[p].z), rnd_tf32(wr[p].w));
            *(float4*)&As[(id >> 3) * ASTR + (id & 7) * 4] = xv4;
            *(float4*)&Ws[(id >> 5) * WSTR + (id & 31) * 4] = wv4;
        }
        __syncthreads();

        if (k0 + 32 < DM) {
#pragma unroll
            for (int p = 0; p < 4; p++) {
                int id = tid + 256 * p;
                xr[p] = *(const float4*)&X[(size_t)(tileM + (id >> 3)) * DM + k0 + 32 + (id & 7) * 4];
                wr[p] = *(const float4*)&W[(size_t)(k0 + 32 + (id >> 5)) * DM + tileN + (id & 31) * 4];
            }
        }

#pragma unroll
        for (int ks = 0; ks < 4; ks++) {
            uint32_t a[4][4];
#pragma unroll
            for (int mt = 0; mt < 4; mt++) {
                uint32_t addr = As_base +
                    4u * (uint32_t)((wm * 64 + mt * 16) * ASTR + ks * 8 + a_lane_off);
                ldsm_x4(a[mt], addr);
            }
            uint32_t bfr[4][2];
#pragma unroll
            for (int nt = 0; nt < 4; nt++) {
                int col = wn * 32 + nt * 8 + (lane >> 2);
                int krow = ks * 8 + (lane & 3);
                bfr[nt][0] = __float_as_uint(Ws[krow * WSTR + col]);
                bfr[nt][1] = __float_as_uint(Ws[(krow + 4) * WSTR + col]);
            }
#pragma unroll
            for (int mt = 0; mt < 4; mt++)
#pragma unroll
                for (int nt = 0; nt < 4; nt++)
                    mma_tf32(acc[mt][nt], a[mt], bfr[nt]);
        }
    }

    // Epilogue: bias + fp16 convert + remap to [b,h,s,d]
#pragma unroll
    for (int mt = 0; mt < 4; mt++) {
        int r0 = tileM + wm * 64 + mt * 16 + (lane >> 2);
#pragma unroll
        for (int nt = 0; nt < 4; nt++) {
            int c0 = tileN + wn * 32 + nt * 8 + (lane & 3) * 2;
            int h = c0 >> 6, d = c0 & 63;
            float bv0 = bias[c0], bv1 = bias[c0 + 1];
#pragma unroll
            for (int half = 0; half < 2; half++) {
                int r = r0 + half * 8;
                int bb = r >> 10, s = r & (SS - 1);
                __half2 o = __floats2half2_rn(acc[mt][nt][half * 2 + 0] + bv0,
                                              acc[mt][nt][half * 2 + 1] + bv1);
                *(__half2*)&out[(((size_t)(bb * NH + h) * SS + s) << 6) + d] = o;
            }
        }
    }
}

// ---------------------------------------------------------------------------
// Fused attention, FP16 mma (m16n8k16). 32 q-rows, 8 warps, full score row
// in smem, 4-buffer 64-row-tile cp.async pipeline (prefetch distance 2).
// K/V slabs fp16 [seq][d] (stride 72 halves). Scores B via normal ldsm.x4;
// PV B via trans ldsm.x4. P stored fp16 overlaid in each score row's own
// fp32 slot (row fully register-resident before the overwrite).
// smem layout (bytes): sQ 4608 | 4 x 9216 slabs | 32 x 4112 score rows.
// ---------------------------------------------------------------------------
#define QR 32
#define KTL 64
#define NTK 16
#define KVH 72                  // slab row stride in halves (144 B)
#define SLAB_B 9216             // 64 * 144
#define SQ_B 4608               // 32 * 144
#define SROW_B 4112             // fp32 score row stride (1028 floats)
#define ATTN_SMEM_BYTES (SQ_B + 4 * SLAB_B + QR * SROW_B)   // 173056

__global__ __launch_bounds__(256, 1) void attn_kernel(
    float* __restrict__ ctx_out, float* __restrict__ attn_out)
{
    extern __shared__ char smc[];
    char* sQc   = smc;
    char* slabc = smc + SQ_B;
    char* sSc   = smc + SQ_B + 4 * SLAB_B;

    const int tid  = threadIdx.x;
    const int warp = tid >> 5;      // 0..7
    const int lane = tid & 31;
    const int wmt  = warp >> 2;     // 0..1 : m16 tile
    const int wns  = warp & 3;      // 0..3 : 16-col n-slice
    const int qt = blockIdx.x;
    const int h  = blockIdx.y;
    const int b  = blockIdx.z;

    const __half* Qb = g_Q + ((size_t)(b * NH + h) * SS + qt * QR) * DK;
    const __half* Kb = g_K + (size_t)(b * NH + h) * SS * DK;
    const __half* Vb = g_V + (size_t)(b * NH + h) * SS * DV;

    const uint32_t sQ_u   = (uint32_t)__cvta_generic_to_shared(sQc);
    const uint32_t slab_u = (uint32_t)__cvta_generic_to_shared(slabc);
    const uint32_t sS_u   = (uint32_t)__cvta_generic_to_shared(sSc);

    // A-fragment lane geometry (m16k16): row = (l&7)+((l>>3)&1)*8, k-half = (l>>4)*8
    const int lrow = (lane & 7) + ((lane >> 3) & 1) * 8;
    const int kh8  = (lane >> 4) * 8;

    // Scores B (normal ldsm, K slab [n][k]):
    //   blocks: (n0-7,k0-7)(n0-7,k8-15)(n8-15,k0-7)(n8-15,k8-15) -> r0..r3
    const int sb_nloc = ((lane >> 4) & 1) * 8 + (lane & 7);
    const int sb_k8   = ((lane >> 3) & 1) * 8;
    const int kb_off  = (wns * 16 + sb_nloc) * KVH * 2 + sb_k8 * 2;   // bytes

    // PV B (trans ldsm, V slab [k][d]):
    //   blocks: (k0-7,d0-7)(k8-15,d0-7)(k0-7,d8-15)(k8-15,d8-15) -> r0..r3
    const int vb_kloc = ((lane >> 3) & 1) * 8 + (lane & 7);
    const int vb_d8   = ((lane >> 4) & 1) * 8;
    const int vb_off  = vb_kloc * KVH * 2 + (wns * 16 + vb_d8) * 2;   // bytes

    // prologue: Q (32 rows x 128 B, 1 cp16/thread) + K0 in group 0; K1 group 1
    {
        int row = tid >> 3, c = tid & 7;
        cp16(sQ_u + (uint32_t)(row * 144 + c * 16), &Qb[row * DK + c * 8]);
    }
#pragma unroll
    for (int p = 0; p < 2; p++) {
        int id = tid + 256 * p;
        int row = id >> 3, c = id & 7;
        cp16(slab_u + (uint32_t)(row * 144 + c * 16), &Kb[row * DK + c * 8]);
    }
    CP_COMMIT();
#pragma unroll
    for (int p = 0; p < 2; p++) {
        int id = tid + 256 * p;
        int row = id >> 3, c = id & 7;
        cp16(slab_u + (uint32_t)(SLAB_B + row * 144 + c * 16),
             &Kb[(KTL + row) * DK + c * 8]);
    }
    CP_COMMIT();
    CP_WAIT1();           // Q + K0 done
    __syncthreads();

    // Preload Q A-fragments (fp16): 4 k16-steps
    uint32_t aq[4][4];
#pragma unroll
    for (int ks = 0; ks < 4; ks++)
        ldsm_x4(aq[ks], sQ_u + (uint32_t)((wmt * 16 + lrow) * 144 + (ks * 16 + kh8) * 2));

    // ---- Scores: S = (Q K^T)/8, 16 tiles, prefetch distance 2 ----
    for (int kt = 0; kt < NTK; kt++) {
        {   // issue tile g = kt+2 (K, or V for g >= 16) — same [seq][d] layout
            int g = kt + 2;
            const __half* src = (g < NTK) ? &Kb[(size_t)g * KTL * DK]
                                          : &Vb[(size_t)(g - NTK) * KTL * DV];
            uint32_t nb = slab_u + (uint32_t)((g & 3) * SLAB_B);
#pragma unroll
            for (int p = 0; p < 2; p++) {
                int id = tid + 256 * p;
                int row = id >> 3, c = id & 7;
                cp16(nb + (uint32_t)(row * 144 + c * 16), &src[row * DK + c * 8]);
            }
            CP_COMMIT();
        }
        CP_WAIT2();
        __syncthreads();

        const uint32_t kbuf = slab_u + (uint32_t)((kt & 3) * SLAB_B) + (uint32_t)kb_off;
        float c[2][4];
#pragma unroll
        for (int nt = 0; nt < 2; nt++)
#pragma unroll
            for (int i = 0; i < 4; i++) c[nt][i] = 0.0f;

#pragma unroll
        for (int ks = 0; ks < 4; ks++) {
            uint32_t bfr[4];
            ldsm_x4(bfr, kbuf + (uint32_t)(ks * 32));
            mma_f16(c[0], aq[ks], &bfr[0]);
            mma_f16(c[1], aq[ks], &bfr[2]);
        }
#pragma unroll
        for (int nt = 0; nt < 2; nt++) {
            int r = wmt * 16 + (lane >> 2);
            int col = kt * KTL + wns * 16 + nt * 8 + 2 * (lane & 3);
            *(float2*)(sSc + r * SROW_B + col * 4) =
                make_float2(c[nt][0] * 0.125f, c[nt][1] * 0.125f);
            *(float2*)(sSc + (r + 8) * SROW_B + col * 4) =
                make_float2(c[nt][2] * 0.125f, c[nt][3] * 0.125f);
        }
    }
    __syncthreads();    // all S visible (V0/V1 loads still in flight)

    // ---- Softmax (4 rows/warp); fp32 P -> gmem, fp16 P -> own row slot ----
#pragma unroll
    for (int rr = 0; rr < 4; rr++) {
        int r = warp * 4 + rr;
        float* row = (float*)(sSc + r * SROW_B);
        float mx = -3.0e38f;
#pragma unroll
        for (int k = 0; k < 8; k++) {
            float4 v = *(const float4*)&row[lane * 4 + 128 * k];
            mx = fmaxf(mx, fmaxf(fmaxf(v.x, v.y), fmaxf(v.z, v.w)));
        }
#pragma unroll
        for (int o = 16; o > 0; o >>= 1) mx = fmaxf(mx, __shfl_xor_sync(0xffffffffu, mx, o));
        float sum = 0.0f;
        float4 e[8];
#pragma unroll
        for (int k = 0; k < 8; k++) {
            float4 v = *(const float4*)&row[lane * 4 + 128 * k];
            e[k].x = __expf(v.x - mx); e[k].y = __expf(v.y - mx);
            e[k].z = __expf(v.z - mx); e[k].w = __expf(v.w - mx);
            sum += e[k].x + e[k].y + e[k].z + e[k].w;
        }
#pragma unroll
        for (int o = 16; o > 0; o >>= 1) sum += __shfl_xor_sync(0xffffffffu, sum, o);
        float inv = 1.0f / sum;
        float* arow = attn_out + ((size_t)(b * NH + h) * SS + qt * QR + r) * SS;
        char* prow = sSc + r * SROW_B;   // fp16 overlay: 1024 halves at row start
#pragma unroll
        for (int k = 0; k < 8; k++) {
            float4 p = make_float4(e[k].x * inv, e[k].y * inv, e[k].z * inv, e[k].w * inv);
            *(float4*)&arow[lane * 4 + 128 * k] = p;
            __half2 h01 = __floats2half2_rn(p.x, p.y);
            __half2 h23 = __floats2half2_rn(p.z, p.w);
            *(uint2*)(prow + lane * 8 + 256 * k) =
                make_uint2(*(uint32_t*)&h01, *(uint32_t*)&h23);
        }
    }
    __syncthreads();    // all fp16 P visible before cross-warp ldsm

    // ---- PV: context = P @ V, 16 V tiles, prefetch distance 2 ----
    float acc2[2][4];
#pragma unroll
    for (int nt = 0; nt < 2; nt++)
#pragma unroll
        for (int i = 0; i < 4; i++) acc2[nt][i] = 0.0f;

    for (int vt = 0; vt < NTK; vt++) {
        if (vt + 2 < NTK) {
            const __half* src = &Vb[(size_t)(vt + 2) * KTL * DV];
            uint32_t nb = slab_u + (uint32_t)(((vt + 2) & 3) * SLAB_B);
#pragma unroll
            for (int p = 0; p < 2; p++) {
                int id = tid + 256 * p;
                int row = id >> 3, c = id & 7;
                cp16(nb + (uint32_t)(row * 144 + c * 16), &src[row * DV + c * 8]);
            }
            CP_COMMIT();
        }
        if (vt < NTK - 2)       CP_WAIT2();
        else if (vt == NTK - 2) CP_WAIT1();
        else                    CP_WAIT0();
        __syncthreads();

        const uint32_t vbuf = slab_u + (uint32_t)((vt & 3) * SLAB_B) + (uint32_t)vb_off;
#pragma unroll
        for (int ks = 0; ks < 4; ks++) {
            uint32_t ap[4];
            ldsm_x4(ap, sS_u + (uint32_t)((wmt * 16 + lrow) * SROW_B
                                          + (vt * KTL + ks * 16 + kh8) * 2));
            uint32_t bfr[4];
            ldsm_x4_t(bfr, vbuf + (uint32_t)(ks * 16 * KVH * 2));
            mma_f16(acc2[0], ap, &bfr[0]);
            mma_f16(acc2[1], ap, &bfr[2]);
        }
    }

    // Write context in [b, s, h*64 + d]
#pragma unroll
    for (int nt = 0; nt < 2; nt++) {
        int r = qt * QR + wmt * 16 + (lane >> 2);
        int col = h * DV + wns * 16 + nt * 8 + 2 * (lane & 3);
        *(float2*)&ctx_out[((size_t)b * SS + r) * (NH * DV) + col] =
            make_float2(acc2[nt][0], acc2[nt][1]);
        *(float2*)&ctx_out[((size_t)b * SS + r + 8) * (NH * DV) + col] =
            make_float2(acc2[nt][2], acc2[nt][3]);
    }
}

// ---------------------------------------------------------------------------
// Launch
// ---------------------------------------------------------------------------
extern "C" void kernel_launch(void* const* d_in, const int* in_sizes, int n_in,
                              void* d_out, int out_size)
{
    const float* q  = (const float*)d_in[0];
    const float* k  = (const float*)d_in[1];
    const float* v  = (const float*)d_in[2];
    const float* wq = (const float*)d_in[3];
    const float* wk = (const float*)d_in[4];
    const float* wv = (const float*)d_in[5];
    const float* bq = (const float*)d_in[6];
    const float* bk = (const float*)d_in[7];
    const float* bv = (const float*)d_in[8];
    // d_in[9] = attn_mask (falsy) -> no masking

    float* ctx  = (float*)d_out;
    float* attn = (float*)d_out + (size_t)BB * SS * NH * DV;

    (void)cudaFuncSetAttribute(attn_kernel,
                               cudaFuncAttributeMaxDynamicSharedMemorySize,
                               ATTN_SMEM_BYTES);

    dim3 pgrid(DM / 128, (BB * SS) / 128, 3);
    proj_mma_kernel<<<pgrid, 256>>>(q, k, v, wq, wk, wv, bq, bk, bv);

    dim3 agrid(SS / QR, NH, BB);
    attn_kernel<<<agrid, 256, ATTN_SMEM_BYTES>>>(ctx, attn);
}

// round 17
// speedup vs baseline: 1.7847x; 1.2888x over previous
#include <cuda_runtime.h>
#include <cuda_fp16.h>
#include <cstdint>
#include <math.h>

// Problem dims
#define BB 4
#define SS 1024
#define DM 1024
#define NH 16
#define DK 64
#define DV 64

// Scratch for projected Q/K/V in [b, h, s, d] layout, stored FP16
__device__ __half g_Q[BB * NH * SS * DK];
__device__ __half g_K[BB * NH * SS * DK];
__device__ __half g_V[BB * NH * SS * DV];

// ---------------------------------------------------------------------------
// helpers
// ---------------------------------------------------------------------------
// fp16 mma, fp32 accumulate
__device__ __forceinline__ void mma_f16(float c[4], const uint32_t a[4], const uint32_t b[2]) {
    asm volatile(
        "mma.sync.aligned.m16n8k16.row.col.f32.f16.f16.f32 "
        "{%0,%1,%2,%3}, {%4,%5,%6,%7}, {%8,%9}, {%0,%1,%2,%3};"
        : "+f"(c[0]), "+f"(c[1]), "+f"(c[2]), "+f"(c[3])
        : "r"(a[0]), "r"(a[1]), "r"(a[2]), "r"(a[3]), "r"(b[0]), "r"(b[1]));
}

__device__ __forceinline__ void ldsm_x4(uint32_t r[4], uint32_t addr) {
    asm volatile("ldmatrix.sync.aligned.m8n8.x4.shared.b16 {%0,%1,%2,%3}, [%4];"
                 : "=r"(r[0]), "=r"(r[1]), "=r"(r[2]), "=r"(r[3]) : "r"(addr));
}
__device__ __forceinline__ void ldsm_x4_t(uint32_t r[4], uint32_t addr) {
    asm volatile("ldmatrix.sync.aligned.m8n8.x4.trans.shared.b16 {%0,%1,%2,%3}, [%4];"
                 : "=r"(r[0]), "=r"(r[1]), "=r"(r[2]), "=r"(r[3]) : "r"(addr));
}

__device__ __forceinline__ void cp16(uint32_t smem, const void* g) {
    asm volatile("cp.async.cg.shared.global [%0], [%1], 16;" :: "r"(smem), "l"(g));
}
#define CP_COMMIT() asm volatile("cp.async.commit_group;")
#define CP_WAIT0()  asm volatile("cp.async.wait_group 0;")
#define CP_WAIT1()  asm volatile("cp.async.wait_group 1;")

// ---------------------------------------------------------------------------
// Projection GEMM, now fp16 m16n8k16 (operands rounded once at smem store).
// Tiles 128x128x32; 8 warps = 2(M) x 4(N); warp tile 64x32.
// As fp16 [128][32] stride 40 halves (80 B: 8 ldsm rows all distinct mod 128).
// Ws fp16 [32][128] stride 136 halves (272 B: rows distinct mod 128).
// ---------------------------------------------------------------------------
#define PASTR 40
#define PWSTR 136

__global__ __launch_bounds__(256, 2) void proj_mma_kernel(
    const float* __restrict__ xq, const float* __restrict__ xk, const float* __restrict__ xv,
    const float* __restrict__ wq, const float* __restrict__ wk, const float* __restrict__ wv,
    const float* __restrict__ bq, const float* __restrict__ bk, const float* __restrict__ bv)
{
    __shared__ __half Ah[128 * PASTR];
    __shared__ __half Wh[32 * PWSTR];

    const float* X; const float* W; const float* bias; __half* out;
    int which = blockIdx.z;
    if (which == 0)      { X = xq; W = wq; bias = bq; out = g_Q; }
    else if (which == 1) { X = xk; W = wk; bias = bk; out = g_K; }
    else                 { X = xv; W = wv; bias = bv; out = g_V; }

    const int tid  = threadIdx.x;
    const int warp = tid >> 5;
    const int lane = tid & 31;
    const int wm   = warp >> 2;   // 0..1
    const int wn   = warp & 3;    // 0..3
    const int tileM = blockIdx.y * 128;
    const int tileN = blockIdx.x * 128;

    // A-frag lane geometry (m16k16)
    const int lrow = (lane & 7) + ((lane >> 3) & 1) * 8;
    const int kh8  = (lane >> 4) * 8;
    // B-frag (trans ldsm over [k][n]): k row + d column select
    const int wkloc = ((lane >> 3) & 1) * 8 + (lane & 7);
    const int wd8   = ((lane >> 4) & 1) * 8;

    const uint32_t Ah_u = (uint32_t)__cvta_generic_to_shared(Ah);
    const uint32_t Wh_u = (uint32_t)__cvta_generic_to_shared(Wh);

    float acc[4][4][4];
#pragma unroll
    for (int mt = 0; mt < 4; mt++)
#pragma unroll
        for (int nt = 0; nt < 4; nt++)
#pragma unroll
            for (int i = 0; i < 4; i++) acc[mt][nt][i] = 0.0f;

    float4 xr[4], wr[4];
#pragma unroll
    for (int p = 0; p < 4; p++) {
        int id = tid + 256 * p;
        xr[p] = *(const float4*)&X[(size_t)(tileM + (id >> 3)) * DM + (id & 7) * 4];
        wr[p] = *(const float4*)&W[(size_t)(id >> 5) * DM + tileN + (id & 31) * 4];
    }

    for (int k0 = 0; k0 < DM; k0 += 32) {
        __syncthreads();
#pragma unroll
        for (int p = 0; p < 4; p++) {
            int id = tid + 256 * p;
            __half2 xh0 = __floats2half2_rn(xr[p].x, xr[p].y);
            __half2 xh1 = __floats2half2_rn(xr[p].z, xr[p].w);
            __half2 wh0 = __floats2half2_rn(wr[p].x, wr[p].y);
            __half2 wh1 = __floats2half2_rn(wr[p].z, wr[p].w);
            *(uint2*)&Ah[(id >> 3) * PASTR + (id & 7) * 4] =
                make_uint2(*(uint32_t*)&xh0, *(uint32_t*)&xh1);
            *(uint2*)&Wh[(id >> 5) * PWSTR + (id & 31) * 4] =
                make_uint2(*(uint32_t*)&wh0, *(uint32_t*)&wh1);
        }
        __syncthreads();

        if (k0 + 32 < DM) {
#pragma unroll
            for (int p = 0; p < 4; p++) {
                int id = tid + 256 * p;
                xr[p] = *(const float4*)&X[(size_t)(tileM + (id >> 3)) * DM + k0 + 32 + (id & 7) * 4];
                wr[p] = *(const float4*)&W[(size_t)(k0 + 32 + (id >> 5)) * DM + tileN + (id & 31) * 4];
            }
        }

#pragma unroll
        for (int ks = 0; ks < 2; ks++) {
            uint32_t a[4][4];
#pragma unroll
            for (int mt = 0; mt < 4; mt++)
                ldsm_x4(a[mt], Ah_u + 2u * (uint32_t)((wm * 64 + mt * 16 + lrow) * PASTR
                                                      + ks * 16 + kh8));
            uint32_t bfr[2][4];
#pragma unroll
            for (int np = 0; np < 2; np++)
                ldsm_x4_t(bfr[np], Wh_u + 2u * (uint32_t)((ks * 16 + wkloc) * PWSTR
                                                          + wn * 32 + np * 16 + wd8));
#pragma unroll
            for (int mt = 0; mt < 4; mt++)
#pragma unroll
                for (int nt = 0; nt < 4; nt++)
                    mma_f16(acc[mt][nt], a[mt], &bfr[nt >> 1][(nt & 1) * 2]);
        }
    }

    // Epilogue: bias + fp16 convert + remap to [b,h,s,d]
#pragma unroll
    for (int mt = 0; mt < 4; mt++) {
        int r0 = tileM + wm * 64 + mt * 16 + (lane >> 2);
#pragma unroll
        for (int nt = 0; nt < 4; nt++) {
            int c0 = tileN + wn * 32 + nt * 8 + (lane & 3) * 2;
            int h = c0 >> 6, d = c0 & 63;
            float bv0 = bias[c0], bv1 = bias[c0 + 1];
#pragma unroll
            for (int half = 0; half < 2; half++) {
                int r = r0 + half * 8;
                int bb = r >> 10, s = r & (SS - 1);
                __half2 o = __floats2half2_rn(acc[mt][nt][half * 2 + 0] + bv0,
                                              acc[mt][nt][half * 2 + 1] + bv1);
                *(__half2*)&out[(((size_t)(bb * NH + h) * SS + s) << 6) + d] = o;
            }
        }
    }
}

// ---------------------------------------------------------------------------
// Fused attention, fp16 mma. 32 q-rows, 8 warps. 128-row K/V tiles (8 K + 8 V),
// 3 slabs, prefetch distance 2, issue-AFTER-compute (3-buffer WAR closed by the
// per-iteration __syncthreads). Scores: warp owns 32 cols (wns*32). PV: 16 d-cols.
// smem: sQ 4608 | 3 x 18432 slabs | 32 x 4112 score rows = 191488 B.
// ---------------------------------------------------------------------------
#define QR 32
#define KTL 128
#define NTK 8
#define KVH 72                  // slab row stride in halves (144 B)
#define SLAB_B 18432            // 128 * 144
#define SQ_B 4608               // 32 * 144
#define SROW_B 4112             // fp32 score row stride
#define ATTN_SMEM_BYTES (SQ_B + 3 * SLAB_B + QR * SROW_B)   // 191488

__global__ __launch_bounds__(256, 1) void attn_kernel(
    float* __restrict__ ctx_out, float* __restrict__ attn_out)
{
    extern __shared__ char smc[];
    char* sQc   = smc;
    char* slabc = smc + SQ_B;
    char* sSc   = smc + SQ_B + 3 * SLAB_B;

    const int tid  = threadIdx.x;
    const int warp = tid >> 5;      // 0..7
    const int lane = tid & 31;
    const int wmt  = warp >> 2;     // 0..1 : m16 tile
    const int wns  = warp & 3;      // 0..3 : n-slice
    const int qt = blockIdx.x;
    const int h  = blockIdx.y;
    const int b  = blockIdx.z;

    const __half* Qb = g_Q + ((size_t)(b * NH + h) * SS + qt * QR) * DK;
    const __half* Kb = g_K + (size_t)(b * NH + h) * SS * DK;
    const __half* Vb = g_V + (size_t)(b * NH + h) * SS * DV;

    const uint32_t sQ_u   = (uint32_t)__cvta_generic_to_shared(sQc);
    const uint32_t slab_u = (uint32_t)__cvta_generic_to_shared(slabc);
    const uint32_t sS_u   = (uint32_t)__cvta_generic_to_shared(sSc);

    const int lrow = (lane & 7) + ((lane >> 3) & 1) * 8;
    const int kh8  = (lane >> 4) * 8;

    // Scores B (normal ldsm, K slab [n][k])
    const int sb_nloc = ((lane >> 4) & 1) * 8 + (lane & 7);
    const int sb_k8   = ((lane >> 3) & 1) * 8;
    // PV B (trans ldsm, V slab [k][d])
    const int vb_kloc = ((lane >> 3) & 1) * 8 + (lane & 7);
    const int vb_d8   = ((lane >> 4) & 1) * 8;
    const int vb_off  = vb_kloc * KVH * 2 + (wns * 16 + vb_d8) * 2;   // bytes

    // ---- tile issue: 128 rows x 128 B = 1024 cp16, 4/thread ----
    auto issue_tile = [&](const __half* src, int buf) {
        uint32_t nb = slab_u + (uint32_t)(buf * SLAB_B);
#pragma unroll
        for (int p = 0; p < 4; p++) {
            int id = tid + 256 * p;
            int row = id >> 3, c = id & 7;
            cp16(nb + (uint32_t)(row * 144 + c * 16), &src[row * DK + c * 8]);
        }
        CP_COMMIT();
    };

    // prologue: Q (1 cp16/thread) + K0 in group 0; K1 group 1
    {
        int row = tid >> 3, c = tid & 7;
        cp16(sQ_u + (uint32_t)(row * 144 + c * 16), &Qb[row * DK + c * 8]);
    }
    issue_tile(&Kb[0], 0);                 // group 0 (with Q)
    issue_tile(&Kb[(size_t)KTL * DK], 1);  // group 1
    CP_WAIT1();                            // Q + K0 done
    __syncthreads();

    // Preload Q A-fragments (fp16): 4 k16-steps
    uint32_t aq[4][4];
#pragma unroll
    for (int ks = 0; ks < 4; ks++)
        ldsm_x4(aq[ks], sQ_u + (uint32_t)((wmt * 16 + lrow) * 144 + (ks * 16 + kh8) * 2));

    // ---- Scores: S = (Q K^T)/8, 8 tiles of 128 rows ----
    for (int kt = 0; kt < NTK; kt++) {
        CP_WAIT1();        // tile kt done (kt+1 pending)
        __syncthreads();

        const uint32_t kbuf = slab_u + (uint32_t)((kt % 3) * SLAB_B);
        float c[4][4];
#pragma unroll
        for (int nt = 0; nt < 4; nt++)
#pragma unroll
            for (int i = 0; i < 4; i++) c[nt][i] = 0.0f;

#pragma unroll
        for (int ks = 0; ks < 4; ks++) {
            uint32_t bfr[2][4];
#pragma unroll
            for (int np = 0; np < 2; np++)
                ldsm_x4(bfr[np], kbuf + (uint32_t)((wns * 32 + np * 16 + sb_nloc) * KVH * 2
                                                   + (ks * 16 + sb_k8) * 2));
#pragma unroll
            for (int nt = 0; nt < 4; nt++)
                mma_f16(c[nt], aq[ks], &bfr[nt >> 1][(nt & 1) * 2]);
        }
#pragma unroll
        for (int nt = 0; nt < 4; nt++) {
            int r = wmt * 16 + (lane >> 2);
            int col = kt * KTL + wns * 32 + nt * 8 + 2 * (lane & 3);
            *(float2*)(sSc + r * SROW_B + col * 4) =
                make_float2(c[nt][0] * 0.125f, c[nt][1] * 0.125f);
            *(float2*)(sSc + (r + 8) * SROW_B + col * 4) =
                make_float2(c[nt][2] * 0.125f, c[nt][3] * 0.125f);
        }

        // issue tile kt+2 AFTER compute (3-buffer WAR closed by sync above)
        int g = kt + 2;
        if (g < NTK)       issue_tile(&Kb[(size_t)g * KTL * DK], g % 3);
        else if (g < 2 * NTK) issue_tile(&Vb[(size_t)(g - NTK) * KTL * DV], g % 3);
    }
    __syncthreads();    // all S visible (V0/V1 in flight)

    // ---- Softmax (4 rows/warp); fp32 P -> gmem, fp16 P -> own row slot ----
#pragma unroll
    for (int rr = 0; rr < 4; rr++) {
        int r = warp * 4 + rr;
        float* row = (float*)(sSc + r * SROW_B);
        float mx = -3.0e38f;
#pragma unroll
        for (int k = 0; k < 8; k++) {
            float4 v = *(const float4*)&row[lane * 4 + 128 * k];
            mx = fmaxf(mx, fmaxf(fmaxf(v.x, v.y), fmaxf(v.z, v.w)));
        }
#pragma unroll
        for (int o = 16; o > 0; o >>= 1) mx = fmaxf(mx, __shfl_xor_sync(0xffffffffu, mx, o));
        float sum = 0.0f;
        float4 e[8];
#pragma unroll
        for (int k = 0; k < 8; k++) {
            float4 v = *(const float4*)&row[lane * 4 + 128 * k];
            e[k].x = __expf(v.x - mx); e[k].y = __expf(v.y - mx);
            e[k].z = __expf(v.z - mx); e[k].w = __expf(v.w - mx);
            sum += e[k].x + e[k].y + e[k].z + e[k].w;
        }
#pragma unroll
        for (int o = 16; o > 0; o >>= 1) sum += __shfl_xor_sync(0xffffffffu, sum, o);
        float inv = 1.0f / sum;
        float* arow = attn_out + ((size_t)(b * NH + h) * SS + qt * QR + r) * SS;
        char* prow = sSc + r * SROW_B;   // fp16 overlay at row start
#pragma unroll
        for (int k = 0; k < 8; k++) {
            float4 p = make_float4(e[k].x * inv, e[k].y * inv, e[k].z * inv, e[k].w * inv);
            *(float4*)&arow[lane * 4 + 128 * k] = p;
            __half2 h01 = __floats2half2_rn(p.x, p.y);
            __half2 h23 = __floats2half2_rn(p.z, p.w);
            *(uint2*)(prow + lane * 8 + 256 * k) =
                make_uint2(*(uint32_t*)&h01, *(uint32_t*)&h23);
        }
    }
    __syncthreads();    // fp16 P visible before cross-warp ldsm

    // ---- PV: context = P @ V, 8 V tiles of 128 rows ----
    float acc2[2][4];
#pragma unroll
    for (int nt = 0; nt < 2; nt++)
#pragma unroll
        for (int i = 0; i < 4; i++) acc2[nt][i] = 0.0f;

    for (int vt = 0; vt < NTK; vt++) {
        if (vt < NTK - 1) CP_WAIT1();
        else              CP_WAIT0();
        __syncthreads();

        const uint32_t vbuf = slab_u + (uint32_t)(((vt + NTK) % 3) * SLAB_B) + (uint32_t)vb_off;
#pragma unroll
        for (int ks = 0; ks < 8; ks++) {
            uint32_t ap[4];
            ldsm_x4(ap, sS_u + (uint32_t)((wmt * 16 + lrow) * SROW_B
                                          + (vt * KTL + ks * 16 + kh8) * 2));
            uint32_t bfr[4];
            ldsm_x4_t(bfr, vbuf + (uint32_t)(ks * 16 * KVH * 2));
            mma_f16(acc2[0], ap, &bfr[0]);
            mma_f16(acc2[1], ap, &bfr[2]);
        }

        if (vt + 2 < NTK)
            issue_tile(&Vb[(size_t)(vt + 2) * KTL * DV], (vt + 2 + NTK) % 3);
    }

    // Write context in [b, s, h*64 + d]
#pragma unroll
    for (int nt = 0; nt < 2; nt++) {
        int r = qt * QR + wmt * 16 + (lane >> 2);
        int col = h * DV + wns * 16 + nt * 8 + 2 * (lane & 3);
        *(float2*)&ctx_out[((size_t)b * SS + r) * (NH * DV) + col] =
            make_float2(acc2[nt][0], acc2[nt][1]);
        *(float2*)&ctx_out[((size_t)b * SS + r + 8) * (NH * DV) + col] =
            make_float2(acc2[nt][2], acc2[nt][3]);
    }
}

// ---------------------------------------------------------------------------
// Launch
// ---------------------------------------------------------------------------
extern "C" void kernel_launch(void* const* d_in, const int* in_sizes, int n_in,
                              void* d_out, int out_size)
{
    const float* q  = (const float*)d_in[0];
    const float* k  = (const float*)d_in[1];
    const float* v  = (const float*)d_in[2];
    const float* wq = (const float*)d_in[3];
    const float* wk = (const float*)d_in[4];
    const float* wv = (const float*)d_in[5];
    const float* bq = (const float*)d_in[6];
    const float* bk = (const float*)d_in[7];
    const float* bv = (const float*)d_in[8];
    // d_in[9] = attn_mask (falsy) -> no masking

    float* ctx  = (float*)d_out;
    float* attn = (float*)d_out + (size_t)BB * SS * NH * DV;

    (void)cudaFuncSetAttribute(attn_kernel,
                               cudaFuncAttributeMaxDynamicSharedMemorySize,
                               ATTN_SMEM_BYTES);

    dim3 pgrid(DM / 128, (BB * SS) / 128, 3);
    proj_mma_kernel<<<pgrid, 256>>>(q, k, v, wq, wk, wv, bq, bk, bv);

    dim3 agrid(SS / QR, NH, BB);
    attn_kernel<<<agrid, 256, ATTN_SMEM_BYTES>>>(ctx, attn);
}